// round 6
// baseline (speedup 1.0000x reference)
#include <cuda_runtime.h>
#include <cuda_bf16.h>
#include <cstdint>

// ---------------------------------------------------------------------------
// centercompute: per-class mean of [N, 256] f32 features (4 classes), then
// L2-normalize each class center. Output: fea_center [4,256] f32 (+ target
// arange(4) if out_size allows).
//
// NOTE: labels arrive as int32 (JAX x64-disabled downgrades jnp.int64).
//
// Stage 1 (seg_sum): grid-stride over rows. 256 thr/block; thread t owns
//   float4 column (t & 63) of row-slot (t >> 6). 64 threads/row -> every
//   warp processes ONE row -> label branch is warp-uniform (no divergence).
//   Unroll 4 rows/thread/iter for MLP. Accumulate with packed add.rn.f32x2.
//   Block-reduce the 4 row-slots in shared, write per-block partials to
//   __device__ scratch (deterministic: no float atomics).
// Stage 2 (count): per-block label histogram -> int partials (exact).
// Stage 3 (finalize): 1 block x 1024 threads reduces partials in fixed
//   order, computes mean, per-class L2 norm via shuffle+shared, writes out.
// ---------------------------------------------------------------------------

#define NB 608          // stage-1 / count grid size (152 SMs * 4)
#define NCLS 4

__device__ ulonglong2 g_partials[NB * NCLS * 64];  // [block][class][64 x float4]
__device__ int        g_cnt[NB * NCLS];

static __device__ __forceinline__ unsigned long long f32x2_add(
    unsigned long long a, unsigned long long b) {
    unsigned long long r;
    asm("add.rn.f32x2 %0, %1, %2;" : "=l"(r) : "l"(a), "l"(b));
    return r;
}

static __device__ __forceinline__ void vadd(ulonglong2& a, const ulonglong2& v) {
    a.x = f32x2_add(a.x, v.x);
    a.y = f32x2_add(a.y, v.y);
}

__global__ __launch_bounds__(256) void seg_sum_kernel(
    const ulonglong2* __restrict__ feat,   // [N, 64] 16B packs (256 f32/row)
    const int*        __restrict__ labels, // [N] int32
    int n)
{
    const int tid  = threadIdx.x;
    const int col  = tid & 63;   // float4 column 0..63
    const int rsub = tid >> 6;   // row slot 0..3

    ulonglong2 acc[NCLS];
#pragma unroll
    for (int c = 0; c < NCLS; c++) { acc[c].x = 0ull; acc[c].y = 0ull; }

    const int stride = gridDim.x * 16;
    for (int base = blockIdx.x * 16; base < n; base += stride) {
        int        lv[4];
        ulonglong2 v[4];
        // ---- batched loads (4 independent LDG.128 in flight) ----
#pragma unroll
        for (int u = 0; u < 4; u++) {
            int r = base + rsub + 4 * u;
            if (r < n) {
                lv[u] = labels[r];                      // warp-uniform (L1 bcast)
                v[u]  = feat[(size_t)r * 64 + col];
            } else {
                lv[u] = -1;
            }
        }
        // ---- warp-uniform class branch: adds for ONE class per row ----
#pragma unroll
        for (int u = 0; u < 4; u++) {
            int cl = lv[u];
            if      (cl == 0) vadd(acc[0], v[u]);
            else if (cl == 1) vadd(acc[1], v[u]);
            else if (cl == 2) vadd(acc[2], v[u]);
            else if (cl == 3) vadd(acc[3], v[u]);
        }
    }

    // ---- block reduction across the 4 row slots, write partials ----
    __shared__ ulonglong2 sh[256];
#pragma unroll
    for (int c = 0; c < NCLS; c++) {
        sh[tid] = acc[c];
        __syncthreads();
        if (tid < 64) {
            ulonglong2 s = sh[tid];
            vadd(s, sh[tid + 64]);
            vadd(s, sh[tid + 128]);
            vadd(s, sh[tid + 192]);
            g_partials[((size_t)blockIdx.x * NCLS + c) * 64 + tid] = s;
        }
        __syncthreads();
    }
}

__global__ __launch_bounds__(256) void count_kernel(
    const int* __restrict__ labels, int n)
{
    __shared__ int s[NCLS];
    if (threadIdx.x < NCLS) s[threadIdx.x] = 0;
    __syncthreads();

    int c0 = 0, c1 = 0, c2 = 0, c3 = 0;
    for (int i = blockIdx.x * blockDim.x + threadIdx.x; i < n;
         i += gridDim.x * blockDim.x) {
        int l = labels[i];
        c0 += (l == 0); c1 += (l == 1); c2 += (l == 2); c3 += (l == 3);
    }
    atomicAdd(&s[0], c0);  // int atomics: exact, order-independent
    atomicAdd(&s[1], c1);
    atomicAdd(&s[2], c2);
    atomicAdd(&s[3], c3);
    __syncthreads();
    if (threadIdx.x < NCLS)
        g_cnt[blockIdx.x * NCLS + threadIdx.x] = s[threadIdx.x];
}

__global__ __launch_bounds__(1024) void finalize_kernel(
    float* __restrict__ out, int out_size)
{
    __shared__ float scount[NCLS];
    __shared__ float wsum[32];
    __shared__ float sinv[NCLS];

    const int j   = threadIdx.x;       // 0..1023
    const int c   = j >> 8;            // class 0..3
    const int col = j & 255;           // column 0..255

    if (j < NCLS) {
        int s = 0;
        for (int b = 0; b < NB; b++) s += g_cnt[b * NCLS + j];
        scount[j] = (float)s;
    }
    __syncthreads();

    // deterministic fixed-order reduction over per-block partials
    const float* p = reinterpret_cast<const float*>(g_partials);
    float sum = 0.0f;
    int b = 0;
#pragma unroll 4
    for (; b + 4 <= NB; b += 4) {
        sum += p[((b + 0) * NCLS + c) * 256 + col];
        sum += p[((b + 1) * NCLS + c) * 256 + col];
        sum += p[((b + 2) * NCLS + c) * 256 + col];
        sum += p[((b + 3) * NCLS + c) * 256 + col];
    }
    for (; b < NB; b++) sum += p[(b * NCLS + c) * 256 + col];

    const float mean = sum / scount[c];

    // per-class L2 norm: 256 threads/class = 8 warps/class
    float m2 = mean * mean;
#pragma unroll
    for (int o = 16; o > 0; o >>= 1)
        m2 += __shfl_down_sync(0xFFFFFFFFu, m2, o);
    if ((j & 31) == 0) wsum[j >> 5] = m2;
    __syncthreads();
    if (j < NCLS) {
        float t = 0.0f;
#pragma unroll
        for (int w = 0; w < 8; w++) t += wsum[j * 8 + w];
        float nrm = sqrtf(t);
        sinv[j] = 1.0f / fmaxf(nrm, 1e-12f);
    }
    __syncthreads();

    if (j < out_size) out[j] = mean * sinv[c];

    // target = arange(4), appended after the 1024 center floats if present
    int k = 1024 + j;
    if (j < NCLS && k < out_size) out[k] = (float)j;
}

extern "C" void kernel_launch(void* const* d_in, const int* in_sizes, int n_in,
                              void* d_out, int out_size)
{
    const ulonglong2* feat   = (const ulonglong2*)d_in[0];  // [N,256] f32
    const int*        labels = (const int*)d_in[1];         // [N] int32
    const int n = in_sizes[1];                              // rows

    seg_sum_kernel<<<NB, 256>>>(feat, labels, n);
    count_kernel<<<NB, 256>>>(labels, n);
    finalize_kernel<<<1, 1024>>>((float*)d_out, out_size);
}

// round 8
// speedup vs baseline: 1.0712x; 1.0712x over previous
#include <cuda_runtime.h>
#include <cuda_bf16.h>
#include <cstdint>

// ---------------------------------------------------------------------------
// centercompute: per-class mean of [N, 256] f32 features (4 classes), then
// L2-normalize each class center. Output: fea_center [4,256] f32 (+ target
// arange(4) if out_size allows). Labels are int32 on device.
//
// Stage 1 (seg_sum, fused count): grid-stride over rows, 256 thr/block;
//   thread t owns float4 column (t & 63) of row-slot (t >> 6). 64 thr/row ->
//   warp-uniform label branch. 4 rows/thread/iter batched LDG.128 for MLP.
//   Packed add.rn.f32x2 accumulate. col==0 thread of each row-group counts
//   labels (integer). Block-reduces both -> per-block partials (deterministic).
// Stage 2 (reduce): 32 blocks x 1024 thr, each sums 19 stage-1 partial
//   vectors coalesced (608 = 32*19) -> 32 x 1024 floats.
// Stage 3 (finalize): 1 block x 1024 thr sums 32 second-level partials +
//   608 int counts in fixed order, normalizes, writes out.
// ---------------------------------------------------------------------------

#define NB   608        // stage-1 grid (152 SMs * 4)
#define NB2  32         // reduce grid; NB = NB2 * 19
#define REDW 19
#define NCLS 4

__device__ ulonglong2 g_partials [NB  * NCLS * 64]; // [block][class][64 x float4]
__device__ float      g_partials2[NB2 * 1024];      // [block2][class*256+col]
__device__ int        g_cnt[NB * NCLS];

static __device__ __forceinline__ unsigned long long f32x2_add(
    unsigned long long a, unsigned long long b) {
    unsigned long long r;
    asm("add.rn.f32x2 %0, %1, %2;" : "=l"(r) : "l"(a), "l"(b));
    return r;
}

static __device__ __forceinline__ void vadd(ulonglong2& a, const ulonglong2& v) {
    a.x = f32x2_add(a.x, v.x);
    a.y = f32x2_add(a.y, v.y);
}

__global__ __launch_bounds__(256) void seg_sum_kernel(
    const ulonglong2* __restrict__ feat,   // [N, 64] 16B packs (256 f32/row)
    const int*        __restrict__ labels, // [N] int32
    int n)
{
    const int tid  = threadIdx.x;
    const int col  = tid & 63;   // float4 column 0..63
    const int rsub = tid >> 6;   // row slot 0..3

    ulonglong2 acc[NCLS];
#pragma unroll
    for (int c = 0; c < NCLS; c++) { acc[c].x = 0ull; acc[c].y = 0ull; }
    int cnt0 = 0, cnt1 = 0, cnt2 = 0, cnt3 = 0;   // used only when col==0

    const int stride = gridDim.x * 16;
    for (int base = blockIdx.x * 16; base < n; base += stride) {
        int        lv[4];
        ulonglong2 v[4];
        // ---- batched loads (4 independent LDG.128 in flight) ----
#pragma unroll
        for (int u = 0; u < 4; u++) {
            int r = base + rsub + 4 * u;
            if (r < n) {
                lv[u] = labels[r];                 // warp-uniform (L1 bcast)
                v[u]  = feat[(size_t)r * 64 + col];
            } else {
                lv[u] = -1;
            }
        }
        // ---- warp-uniform class branch: adds for ONE class per row ----
#pragma unroll
        for (int u = 0; u < 4; u++) {
            int cl = lv[u];
            if      (cl == 0) vadd(acc[0], v[u]);
            else if (cl == 1) vadd(acc[1], v[u]);
            else if (cl == 2) vadd(acc[2], v[u]);
            else if (cl == 3) vadd(acc[3], v[u]);
        }
        // ---- fused label count: one thread per row-group ----
        if (col == 0) {
#pragma unroll
            for (int u = 0; u < 4; u++) {
                cnt0 += (lv[u] == 0); cnt1 += (lv[u] == 1);
                cnt2 += (lv[u] == 2); cnt3 += (lv[u] == 3);
            }
        }
    }

    // ---- block reduction across the 4 row slots, write partials ----
    __shared__ ulonglong2 sh[256];
#pragma unroll
    for (int c = 0; c < NCLS; c++) {
        sh[tid] = acc[c];
        __syncthreads();
        if (tid < 64) {
            ulonglong2 s = sh[tid];
            vadd(s, sh[tid + 64]);
            vadd(s, sh[tid + 128]);
            vadd(s, sh[tid + 192]);
            g_partials[((size_t)blockIdx.x * NCLS + c) * 64 + tid] = s;
        }
        __syncthreads();
    }

    // ---- integer count reduction (4 contributing threads: tid 0,64,128,192)
    __shared__ int scnt[4 * NCLS];
    if (col == 0) {
        scnt[rsub * NCLS + 0] = cnt0;
        scnt[rsub * NCLS + 1] = cnt1;
        scnt[rsub * NCLS + 2] = cnt2;
        scnt[rsub * NCLS + 3] = cnt3;
    }
    __syncthreads();
    if (tid < NCLS)
        g_cnt[blockIdx.x * NCLS + tid] =
            scnt[tid] + scnt[NCLS + tid] + scnt[2 * NCLS + tid] + scnt[3 * NCLS + tid];
}

__global__ __launch_bounds__(1024) void reduce_kernel()
{
    const int j  = threadIdx.x;          // 0..1023 (class*256 + col)
    const int b0 = blockIdx.x * REDW;    // first stage-1 block of this slice
    const float* p = reinterpret_cast<const float*>(g_partials);

    float s = 0.0f;
#pragma unroll 4
    for (int k = 0; k < REDW; k++)       // coalesced: consecutive j -> consecutive floats
        s += p[(size_t)(b0 + k) * 1024 + j];
    g_partials2[blockIdx.x * 1024 + j] = s;
}

__global__ __launch_bounds__(1024) void finalize_kernel(
    float* __restrict__ out, int out_size)
{
    __shared__ float scount[NCLS];
    __shared__ float wsum[32];
    __shared__ float sinv[NCLS];

    const int j = threadIdx.x;           // 0..1023
    const int c = j >> 8;                // class 0..3

    if (j < NCLS) {
        int s = 0;
        for (int b = 0; b < NB; b++) s += g_cnt[b * NCLS + j];
        scount[j] = (float)s;
    }
    __syncthreads();

    // deterministic fixed-order reduction over second-level partials
    float sum = 0.0f;
#pragma unroll 8
    for (int b = 0; b < NB2; b++)
        sum += g_partials2[b * 1024 + j];

    const float mean = sum / scount[c];

    // per-class L2 norm: 256 threads/class = 8 warps/class
    float m2 = mean * mean;
#pragma unroll
    for (int o = 16; o > 0; o >>= 1)
        m2 += __shfl_down_sync(0xFFFFFFFFu, m2, o);
    if ((j & 31) == 0) wsum[j >> 5] = m2;
    __syncthreads();
    if (j < NCLS) {
        float t = 0.0f;
#pragma unroll
        for (int w = 0; w < 8; w++) t += wsum[j * 8 + w];
        float nrm = sqrtf(t);
        sinv[j] = 1.0f / fmaxf(nrm, 1e-12f);
    }
    __syncthreads();

    if (j < out_size) out[j] = mean * sinv[c];

    // target = arange(4), appended after the 1024 center floats if present
    int k = 1024 + j;
    if (j < NCLS && k < out_size) out[k] = (float)j;
}

extern "C" void kernel_launch(void* const* d_in, const int* in_sizes, int n_in,
                              void* d_out, int out_size)
{
    const ulonglong2* feat   = (const ulonglong2*)d_in[0];  // [N,256] f32
    const int*        labels = (const int*)d_in[1];         // [N] int32
    const int n = in_sizes[1];                              // rows

    seg_sum_kernel<<<NB, 256>>>(feat, labels, n);
    reduce_kernel<<<NB2, 1024>>>();
    finalize_kernel<<<1, 1024>>>((float*)d_out, out_size);
}